// round 6
// baseline (speedup 1.0000x reference)
#include <cuda_runtime.h>
#include <cstdint>

#define IN_CH   512
#define HID     16
#define OUT_CH  2
#define MAX_NODES 100000

#define CHUNK_ROWS 16
#define ROW_BYTES  (IN_CH * 4)                 // 2048
#define STAGE_BYTES (CHUNK_ROWS * ROW_BYTES)   // 32768
#define NSTAGES 4
#define DEG_BLOCKS 20
#define THREADS 288                            // 8 consumer warps + 1 producer warp

// Scratch (device globals; no allocation allowed)
__device__ __align__(16) float g_s[MAX_NODES * 2];   // y = x@W12, then s = y*dinv
__device__ __align__(16) int   g_deg[MAX_NODES];     // zero-init; re-zeroed in finalize
__device__ __align__(16) float g_dinv[MAX_NODES];    // 1/sqrt(deg+1)
__device__ float g_c[2];                             // b1@W2 + b2

// ---------------------------------------------------------------------------
__device__ __forceinline__ uint32_t smem_u32(const void* p) {
    uint32_t a;
    asm("{ .reg .u64 t; cvta.to.shared.u64 t, %1; cvt.u32.u64 %0, t; }"
        : "=r"(a) : "l"(p));
    return a;
}
__device__ __forceinline__ void mbar_init(uint32_t mbar, uint32_t cnt) {
    asm volatile("mbarrier.init.shared.b64 [%0], %1;" :: "r"(mbar), "r"(cnt) : "memory");
}
__device__ __forceinline__ void mbar_expect_tx(uint32_t mbar, uint32_t bytes) {
    asm volatile("mbarrier.arrive.expect_tx.shared.b64 _, [%0], %1;"
                 :: "r"(mbar), "r"(bytes) : "memory");
}
__device__ __forceinline__ void mbar_arrive(uint32_t mbar) {
    asm volatile("mbarrier.arrive.shared.b64 _, [%0];" :: "r"(mbar) : "memory");
}
__device__ __forceinline__ void mbar_wait(uint32_t mbar, uint32_t parity) {
    asm volatile(
        "{\n\t"
        ".reg .pred P;\n\t"
        "WAIT_%=:\n\t"
        "mbarrier.try_wait.parity.acquire.cta.shared::cta.b64 P, [%0], %1, 0x989680;\n\t"
        "@P bra.uni DONE_%=;\n\t"
        "bra.uni WAIT_%=;\n\t"
        "DONE_%=:\n\t"
        "}"
        :: "r"(mbar), "r"(parity) : "memory");
}
__device__ __forceinline__ void bulk_copy_g2s(uint32_t dst_smem, const void* src,
                                              uint32_t bytes, uint32_t mbar) {
    asm volatile(
        "cp.async.bulk.shared::cluster.global.mbarrier::complete_tx::bytes "
        "[%0], [%1], %2, [%3];"
        :: "r"(dst_smem), "l"(src), "r"(bytes), "r"(mbar) : "memory");
}

// ---------------------------------------------------------------------------
// K1: fused  deg atomics (blocks [0,DEG_BLOCKS))  ||  GEMM y = x@W12 (rest)
// GEMM: cp.async.bulk pipeline, NSTAGES x 32KB dynamic smem, producer warp 8.
__global__ void __launch_bounds__(THREADS, 1)
fused_kernel(const float* __restrict__ x,
             const int* __restrict__ col,
             const float* __restrict__ W1,
             const float* __restrict__ W2,
             int n_edges, int n_nodes, int n_gemm_blocks) {
    extern __shared__ __align__(1024) char s_buf[];   // NSTAGES * STAGE_BYTES
    __shared__ float sw0[IN_CH];
    __shared__ float sw1[IN_CH];
    __shared__ __align__(8) uint64_t s_full[NSTAGES];
    __shared__ __align__(8) uint64_t s_empty[NSTAGES];

    const int tid = threadIdx.x;

    if ((int)blockIdx.x < DEG_BLOCKS) {
        // ---- degree atomics over edges ----
        int n4 = n_edges >> 2;
        int stride = DEG_BLOCKS * THREADS;
        for (int t = blockIdx.x * THREADS + tid; t < n4; t += stride) {
            int4 c = __ldg(reinterpret_cast<const int4*>(col) + t);
            atomicAdd(&g_deg[c.x], 1);
            atomicAdd(&g_deg[c.y], 1);
            atomicAdd(&g_deg[c.z], 1);
            atomicAdd(&g_deg[c.w], 1);
        }
        if (blockIdx.x == 0 && tid < (n_edges & 3))
            atomicAdd(&g_deg[col[(n4 << 2) + tid]], 1);
        return;
    }

    // ---- fold W12 = W1@W2 into smem ----
    for (int ch = tid; ch < IN_CH; ch += THREADS) {
        float s0 = 0.f, s1 = 0.f;
#pragma unroll
        for (int h = 0; h < HID; h++) {
            float w = __ldg(&W1[ch * HID + h]);
            s0 += w * __ldg(&W2[h * OUT_CH + 0]);
            s1 += w * __ldg(&W2[h * OUT_CH + 1]);
        }
        sw0[ch] = s0;
        sw1[ch] = s1;
    }
    if (tid == 0) {
#pragma unroll
        for (int s = 0; s < NSTAGES; s++) {
            mbar_init(smem_u32(&s_full[s]), 1);       // producer expect_tx arrives
            mbar_init(smem_u32(&s_empty[s]), 256);    // 8 consumer warps arrive
        }
        asm volatile("fence.proxy.async.shared::cta;" ::: "memory");
    }
    __syncthreads();

    const int bid_g   = (int)blockIdx.x - DEG_BLOCKS;
    const int n_chunks = (n_nodes + CHUNK_ROWS - 1) / CHUNK_ROWS;
    const int warp = tid >> 5;
    const int lane = tid & 31;

    if (warp == 8) {
        // ================= producer: bulk copies =================
        if (lane == 0) {
            int k = 0;
            for (int chunk = bid_g; chunk < n_chunks; chunk += n_gemm_blocks, k++) {
                int stage = k & (NSTAGES - 1);
                uint32_t pe = 1u ^ ((k / NSTAGES) & 1);
                mbar_wait(smem_u32(&s_empty[stage]), pe);
                int rows = min(CHUNK_ROWS, n_nodes - chunk * CHUNK_ROWS);
                uint32_t bytes = (uint32_t)rows * ROW_BYTES;
                uint32_t fb = smem_u32(&s_full[stage]);
                mbar_expect_tx(fb, bytes);
                bulk_copy_g2s(smem_u32(s_buf) + stage * STAGE_BYTES,
                              x + (size_t)chunk * CHUNK_ROWS * IN_CH, bytes, fb);
            }
        }
        return;
    }

    // ================= consumers: 8 warps, 2 rows each =================
    float4 wa[4], wb[4];
#pragma unroll
    for (int j = 0; j < 4; j++) {
        int idx = lane + 32 * j;
        wa[j] = reinterpret_cast<const float4*>(sw0)[idx];
        wb[j] = reinterpret_cast<const float4*>(sw1)[idx];
    }

    int k = 0;
    for (int chunk = bid_g; chunk < n_chunks; chunk += n_gemm_blocks, k++) {
        int stage = k & (NSTAGES - 1);
        uint32_t pf = (k / NSTAGES) & 1;
        mbar_wait(smem_u32(&s_full[stage]), pf);

        const float4* base = reinterpret_cast<const float4*>(s_buf + stage * STAGE_BYTES);
        int rows = min(CHUNK_ROWS, n_nodes - chunk * CHUNK_ROWS);
        int ra = warp * 2, rb = warp * 2 + 1;

        float s00 = 0.f, s01 = 0.f, s10 = 0.f, s11 = 0.f;
        if (ra < rows) {
            const float4* pa = base + ra * (IN_CH / 4);
            const float4* pb = base + rb * (IN_CH / 4);
            bool has_b = (rb < rows);
#pragma unroll
            for (int j = 0; j < 4; j++) {
                float4 va = pa[lane + 32 * j];
                s00 += va.x * wa[j].x + va.y * wa[j].y + va.z * wa[j].z + va.w * wa[j].w;
                s01 += va.x * wb[j].x + va.y * wb[j].y + va.z * wb[j].z + va.w * wb[j].w;
            }
            if (has_b) {
#pragma unroll
                for (int j = 0; j < 4; j++) {
                    float4 vb = pb[lane + 32 * j];
                    s10 += vb.x * wa[j].x + vb.y * wa[j].y + vb.z * wa[j].z + vb.w * wa[j].w;
                    s11 += vb.x * wb[j].x + vb.y * wb[j].y + vb.z * wb[j].z + vb.w * wb[j].w;
                }
            }
#pragma unroll
            for (int off = 16; off > 0; off >>= 1) {
                s00 += __shfl_xor_sync(0xFFFFFFFFu, s00, off);
                s01 += __shfl_xor_sync(0xFFFFFFFFu, s01, off);
                s10 += __shfl_xor_sync(0xFFFFFFFFu, s10, off);
                s11 += __shfl_xor_sync(0xFFFFFFFFu, s11, off);
            }
            int rowa = chunk * CHUNK_ROWS + ra;
            if (lane == 0)
                reinterpret_cast<float2*>(g_s)[rowa] = make_float2(s00, s01);
            if (lane == 1 && has_b)
                reinterpret_cast<float2*>(g_s)[rowa + 1] = make_float2(s10, s11);
        }
        mbar_arrive(smem_u32(&s_empty[stage]));
    }
}

// ---------------------------------------------------------------------------
// K2: node prep: dinv = rsqrt(deg+1); s = y*dinv; out = s; fold bias
__global__ void nodeprep_kernel(const float* __restrict__ b1,
                                const float* __restrict__ W2,
                                const float* __restrict__ b2,
                                float* __restrict__ out, int n_nodes) {
    if (blockIdx.x == 0 && threadIdx.x < OUT_CH) {
        int t = threadIdx.x;
        float c = b2[t];
#pragma unroll
        for (int h = 0; h < HID; h++) c += b1[h] * W2[h * OUT_CH + t];
        g_c[t] = c;
    }
    int i = (blockIdx.x * blockDim.x + threadIdx.x) * 2;
    if (i + 1 < n_nodes) {
        float4 y = *reinterpret_cast<float4*>(g_s + i * 2);
        float d0 = rsqrtf((float)(g_deg[i] + 1));
        float d1 = rsqrtf((float)(g_deg[i + 1] + 1));
        y.x *= d0; y.y *= d0; y.z *= d1; y.w *= d1;
        *reinterpret_cast<float4*>(g_s + i * 2) = y;
        *reinterpret_cast<float4*>(out + i * 2) = y;   // accumulator seeded with s[c]
        *reinterpret_cast<float2*>(g_dinv + i) = make_float2(d0, d1);
    } else if (i < n_nodes) {
        float di = rsqrtf((float)(g_deg[i] + 1));
        g_dinv[i] = di;
        float2 y = reinterpret_cast<const float2*>(g_s)[i];
        float2 s = make_float2(y.x * di, y.y * di);
        reinterpret_cast<float2*>(g_s)[i] = s;
        reinterpret_cast<float2*>(out)[i] = s;
    }
}

// ---------------------------------------------------------------------------
// K3: edge scatter  out[c] += s[r]   (8 edges/thread)
__global__ void scatter_kernel(const int* __restrict__ row,
                               const int* __restrict__ col,
                               float* __restrict__ out, int n_edges) {
    int t = blockIdx.x * blockDim.x + threadIdx.x;
    int e = t * 8;
    if (e + 7 < n_edges) {
        int4 r0 = __ldg(reinterpret_cast<const int4*>(row + e));
        int4 r1 = __ldg(reinterpret_cast<const int4*>(row + e + 4));
        int4 c0 = __ldg(reinterpret_cast<const int4*>(col + e));
        int4 c1 = __ldg(reinterpret_cast<const int4*>(col + e + 4));

        float2 s0 = __ldg(reinterpret_cast<const float2*>(g_s) + r0.x);
        float2 s1 = __ldg(reinterpret_cast<const float2*>(g_s) + r0.y);
        float2 s2 = __ldg(reinterpret_cast<const float2*>(g_s) + r0.z);
        float2 s3 = __ldg(reinterpret_cast<const float2*>(g_s) + r0.w);
        float2 s4 = __ldg(reinterpret_cast<const float2*>(g_s) + r1.x);
        float2 s5 = __ldg(reinterpret_cast<const float2*>(g_s) + r1.y);
        float2 s6 = __ldg(reinterpret_cast<const float2*>(g_s) + r1.z);
        float2 s7 = __ldg(reinterpret_cast<const float2*>(g_s) + r1.w);

        asm volatile("red.global.add.v2.f32 [%0], {%1, %2};"
                     :: "l"(out + (size_t)c0.x * 2), "f"(s0.x), "f"(s0.y) : "memory");
        asm volatile("red.global.add.v2.f32 [%0], {%1, %2};"
                     :: "l"(out + (size_t)c0.y * 2), "f"(s1.x), "f"(s1.y) : "memory");
        asm volatile("red.global.add.v2.f32 [%0], {%1, %2};"
                     :: "l"(out + (size_t)c0.z * 2), "f"(s2.x), "f"(s2.y) : "memory");
        asm volatile("red.global.add.v2.f32 [%0], {%1, %2};"
                     :: "l"(out + (size_t)c0.w * 2), "f"(s3.x), "f"(s3.y) : "memory");
        asm volatile("red.global.add.v2.f32 [%0], {%1, %2};"
                     :: "l"(out + (size_t)c1.x * 2), "f"(s4.x), "f"(s4.y) : "memory");
        asm volatile("red.global.add.v2.f32 [%0], {%1, %2};"
                     :: "l"(out + (size_t)c1.y * 2), "f"(s5.x), "f"(s5.y) : "memory");
        asm volatile("red.global.add.v2.f32 [%0], {%1, %2};"
                     :: "l"(out + (size_t)c1.z * 2), "f"(s6.x), "f"(s6.y) : "memory");
        asm volatile("red.global.add.v2.f32 [%0], {%1, %2};"
                     :: "l"(out + (size_t)c1.w * 2), "f"(s7.x), "f"(s7.y) : "memory");
    } else {
        for (; e < n_edges; e++) {
            int r1 = row[e], c1 = col[e];
            float2 sv = __ldg(reinterpret_cast<const float2*>(g_s) + r1);
            asm volatile("red.global.add.v2.f32 [%0], {%1, %2};"
                         :: "l"(out + (size_t)c1 * 2), "f"(sv.x), "f"(sv.y) : "memory");
        }
    }
}

// ---------------------------------------------------------------------------
// K4: finalize: out = out*dinv + c; re-zero g_deg for next deterministic run
__global__ void finalize_kernel(float* __restrict__ out, int n_nodes) {
    int i = (blockIdx.x * blockDim.x + threadIdx.x) * 2;
    float c0 = g_c[0], c1 = g_c[1];
    if (i + 1 < n_nodes) {
        float4 a = *reinterpret_cast<float4*>(out + i * 2);
        float2 d = *reinterpret_cast<float2*>(g_dinv + i);
        a.x = a.x * d.x + c0;  a.y = a.y * d.x + c1;
        a.z = a.z * d.y + c0;  a.w = a.w * d.y + c1;
        *reinterpret_cast<float4*>(out + i * 2) = a;
        *reinterpret_cast<int2*>(g_deg + i) = make_int2(0, 0);
    } else if (i < n_nodes) {
        float di = g_dinv[i];
        float2 a = reinterpret_cast<float2*>(out)[i];
        a.x = a.x * di + c0;
        a.y = a.y * di + c1;
        reinterpret_cast<float2*>(out)[i] = a;
        g_deg[i] = 0;
    }
}

// ---------------------------------------------------------------------------
extern "C" void kernel_launch(void* const* d_in, const int* in_sizes, int n_in,
                              void* d_out, int out_size) {
    const float* x  = (const float*)d_in[0];
    const int*   ei = (const int*)d_in[1];   // [2, E]
    const float* W1 = (const float*)d_in[2];
    const float* b1 = (const float*)d_in[3];
    const float* W2 = (const float*)d_in[4];
    const float* b2 = (const float*)d_in[5];
    float* out = (float*)d_out;

    const int n_edges = in_sizes[1] / 2;
    const int n_nodes = out_size / OUT_CH;
    const int* row = ei;             // source nodes
    const int* col = ei + n_edges;   // target nodes

    int dev = 0, sms = 148;
    cudaGetDevice(&dev);
    cudaDeviceGetAttribute(&sms, cudaDevAttrMultiProcessorCount, dev);

    const int smem_bytes = NSTAGES * STAGE_BYTES;   // 128 KB
    static bool attr_set = false;
    if (!attr_set) {
        cudaFuncSetAttribute(fused_kernel,
                             cudaFuncAttributeMaxDynamicSharedMemorySize, smem_bytes);
        attr_set = true;
    }

    const int T = 256;
    const int n_gemm_blocks = sms - DEG_BLOCKS;
    const int node2_blocks = ((n_nodes + 1) / 2 + T - 1) / T;
    const int edge8_threads = (n_edges + 7) / 8;

    fused_kernel<<<sms, THREADS, smem_bytes>>>(x, col, W1, W2,
                                               n_edges, n_nodes, n_gemm_blocks);
    nodeprep_kernel<<<node2_blocks, T>>>(b1, W2, b2, out, n_nodes);
    scatter_kernel<<<(edge8_threads + T - 1) / T, T>>>(row, col, out, n_edges);
    finalize_kernel<<<node2_blocks, T>>>(out, n_nodes);
}

// round 7
// speedup vs baseline: 1.3596x; 1.3596x over previous
#include <cuda_runtime.h>
#include <cstdint>

#define IN_CH   512
#define HID     16
#define OUT_CH  2
#define MAX_NODES 100000
#define DEG_BLOCKS 64

// Scratch (device globals; no allocation allowed)
__device__ __align__(16) float g_s[MAX_NODES * 2];   // y = x@W12, then s = y*dinv
__device__ __align__(16) int   g_deg[MAX_NODES];     // zero-init; re-zeroed in nodeprep
__device__ __align__(16) float g_dinv[MAX_NODES];    // 1/sqrt(deg+1)
__device__ float g_c[2];                             // b1@W2 + b2

// ---------------------------------------------------------------------------
// K1: persistent fused kernel
//   blocks [0, DEG_BLOCKS): degree atomics over col (+ L2 prefetch of row)
//   blocks [DEG_BLOCKS, G): grid-stride GEMM, warp computes 4 rows/iter,
//                           x read with evict-first (streaming, no L2 pollution)
__global__ void __launch_bounds__(256, 2)
fused_kernel(const float* __restrict__ x,
             const int* __restrict__ row,
             const int* __restrict__ col,
             const float* __restrict__ W1,
             const float* __restrict__ W2,
             int n_edges, int n_nodes) {
    const int tid = threadIdx.x;

    if ((int)blockIdx.x < DEG_BLOCKS) {
        // ---- degree atomics; also warm L2 with row[] for the scatter ----
        int n4 = n_edges >> 2;
        int stride = DEG_BLOCKS * blockDim.x;
        for (int t = blockIdx.x * blockDim.x + tid; t < n4; t += stride) {
            int4 c = __ldg(reinterpret_cast<const int4*>(col) + t);
            if ((t & 7) == 0)   // one 128B line per 8 int4s
                asm volatile("prefetch.global.L2 [%0];"
                             :: "l"(reinterpret_cast<const int4*>(row) + t));
            atomicAdd(&g_deg[c.x], 1);
            atomicAdd(&g_deg[c.y], 1);
            atomicAdd(&g_deg[c.z], 1);
            atomicAdd(&g_deg[c.w], 1);
        }
        if (blockIdx.x == 0 && tid < (n_edges & 3))
            atomicAdd(&g_deg[col[(n4 << 2) + tid]], 1);
        return;
    }

    // ---- fold W12 = W1@W2 into smem (once per persistent block) ----
    __shared__ float sw0[IN_CH];
    __shared__ float sw1[IN_CH];
    for (int ch = tid; ch < IN_CH; ch += blockDim.x) {
        float s0 = 0.f, s1 = 0.f;
#pragma unroll
        for (int h = 0; h < HID; h++) {
            float w = __ldg(&W1[ch * HID + h]);
            s0 += w * __ldg(&W2[h * OUT_CH + 0]);
            s1 += w * __ldg(&W2[h * OUT_CH + 1]);
        }
        sw0[ch] = s0;
        sw1[ch] = s1;
    }
    __syncthreads();

    const int lane    = tid & 31;
    const int gwarp   = ((int)blockIdx.x - DEG_BLOCKS) * 8 + (tid >> 5);
    const int n_warps = ((int)gridDim.x - DEG_BLOCKS) * 8;

    float4 wa[4], wb[4];
#pragma unroll
    for (int j = 0; j < 4; j++) {
        int idx = lane + 32 * j;
        wa[j] = reinterpret_cast<const float4*>(sw0)[idx];
        wb[j] = reinterpret_cast<const float4*>(sw1)[idx];
    }

    const float4* x4 = reinterpret_cast<const float4*>(x);
    const int n_groups = n_nodes >> 2;              // groups of 4 rows

    for (int g = gwarp; g < n_groups; g += n_warps) {
        const int rbase = g * 4;
        float4 v[4][4];
#pragma unroll
        for (int r = 0; r < 4; r++) {
            const float4* xr = x4 + (size_t)(rbase + r) * (IN_CH / 4);
#pragma unroll
            for (int j = 0; j < 4; j++) v[r][j] = __ldcs(xr + lane + 32 * j);
        }
        float s00 = 0.f, s01 = 0.f, s10 = 0.f, s11 = 0.f;
        float s20 = 0.f, s21 = 0.f, s30 = 0.f, s31 = 0.f;
#pragma unroll
        for (int j = 0; j < 4; j++) {
            s00 += v[0][j].x * wa[j].x + v[0][j].y * wa[j].y + v[0][j].z * wa[j].z + v[0][j].w * wa[j].w;
            s01 += v[0][j].x * wb[j].x + v[0][j].y * wb[j].y + v[0][j].z * wb[j].z + v[0][j].w * wb[j].w;
            s10 += v[1][j].x * wa[j].x + v[1][j].y * wa[j].y + v[1][j].z * wa[j].z + v[1][j].w * wa[j].w;
            s11 += v[1][j].x * wb[j].x + v[1][j].y * wb[j].y + v[1][j].z * wb[j].z + v[1][j].w * wb[j].w;
            s20 += v[2][j].x * wa[j].x + v[2][j].y * wa[j].y + v[2][j].z * wa[j].z + v[2][j].w * wa[j].w;
            s21 += v[2][j].x * wb[j].x + v[2][j].y * wb[j].y + v[2][j].z * wb[j].z + v[2][j].w * wb[j].w;
            s30 += v[3][j].x * wa[j].x + v[3][j].y * wa[j].y + v[3][j].z * wa[j].z + v[3][j].w * wa[j].w;
            s31 += v[3][j].x * wb[j].x + v[3][j].y * wb[j].y + v[3][j].z * wb[j].z + v[3][j].w * wb[j].w;
        }
#pragma unroll
        for (int off = 16; off > 0; off >>= 1) {
            s00 += __shfl_xor_sync(0xFFFFFFFFu, s00, off);
            s01 += __shfl_xor_sync(0xFFFFFFFFu, s01, off);
            s10 += __shfl_xor_sync(0xFFFFFFFFu, s10, off);
            s11 += __shfl_xor_sync(0xFFFFFFFFu, s11, off);
            s20 += __shfl_xor_sync(0xFFFFFFFFu, s20, off);
            s21 += __shfl_xor_sync(0xFFFFFFFFu, s21, off);
            s30 += __shfl_xor_sync(0xFFFFFFFFu, s30, off);
            s31 += __shfl_xor_sync(0xFFFFFFFFu, s31, off);
        }
        if (lane < 4) {
            float o0, o1;
            if      (lane == 0) { o0 = s00; o1 = s01; }
            else if (lane == 1) { o0 = s10; o1 = s11; }
            else if (lane == 2) { o0 = s20; o1 = s21; }
            else                { o0 = s30; o1 = s31; }
            reinterpret_cast<float2*>(g_s)[rbase + lane] = make_float2(o0, o1);
        }
    }
    // scalar tail rows (none when n_nodes % 4 == 0)
    for (int r = (n_groups << 2) + gwarp; r < n_nodes; r += n_warps) {
        const float4* xr = x4 + (size_t)r * (IN_CH / 4);
        float s0 = 0.f, s1 = 0.f;
#pragma unroll
        for (int j = 0; j < 4; j++) {
            float4 v0 = __ldcs(xr + lane + 32 * j);
            s0 += v0.x * wa[j].x + v0.y * wa[j].y + v0.z * wa[j].z + v0.w * wa[j].w;
            s1 += v0.x * wb[j].x + v0.y * wb[j].y + v0.z * wb[j].z + v0.w * wb[j].w;
        }
#pragma unroll
        for (int off = 16; off > 0; off >>= 1) {
            s0 += __shfl_xor_sync(0xFFFFFFFFu, s0, off);
            s1 += __shfl_xor_sync(0xFFFFFFFFu, s1, off);
        }
        if (lane == 0)
            reinterpret_cast<float2*>(g_s)[r] = make_float2(s0, s1);
    }
}

// ---------------------------------------------------------------------------
// K2: node prep: dinv = rsqrt(deg+1); s = y*dinv; out = s; re-zero deg; bias
__global__ void nodeprep_kernel(const float* __restrict__ b1,
                                const float* __restrict__ W2,
                                const float* __restrict__ b2,
                                float* __restrict__ out, int n_nodes) {
    if (blockIdx.x == 0 && threadIdx.x < OUT_CH) {
        int t = threadIdx.x;
        float c = b2[t];
#pragma unroll
        for (int h = 0; h < HID; h++) c += b1[h] * W2[h * OUT_CH + t];
        g_c[t] = c;
    }
    int i = (blockIdx.x * blockDim.x + threadIdx.x) * 2;
    if (i + 1 < n_nodes) {
        float4 y = *reinterpret_cast<float4*>(g_s + i * 2);
        float d0 = rsqrtf((float)(g_deg[i] + 1));
        float d1 = rsqrtf((float)(g_deg[i + 1] + 1));
        *reinterpret_cast<int2*>(g_deg + i) = make_int2(0, 0);  // ready for replay
        y.x *= d0; y.y *= d0; y.z *= d1; y.w *= d1;
        *reinterpret_cast<float4*>(g_s + i * 2) = y;
        *reinterpret_cast<float4*>(out + i * 2) = y;   // accumulator seeded with s[c]
        *reinterpret_cast<float2*>(g_dinv + i) = make_float2(d0, d1);
    } else if (i < n_nodes) {
        float di = rsqrtf((float)(g_deg[i] + 1));
        g_deg[i] = 0;
        g_dinv[i] = di;
        float2 y = reinterpret_cast<const float2*>(g_s)[i];
        float2 s = make_float2(y.x * di, y.y * di);
        reinterpret_cast<float2*>(g_s)[i] = s;
        reinterpret_cast<float2*>(out)[i] = s;
    }
}

// ---------------------------------------------------------------------------
// K3: edge scatter  out[c] += s[r]   (8 edges/thread; indices are L2-warm)
__global__ void scatter_kernel(const int* __restrict__ row,
                               const int* __restrict__ col,
                               float* __restrict__ out, int n_edges) {
    int t = blockIdx.x * blockDim.x + threadIdx.x;
    int e = t * 8;
    if (e + 7 < n_edges) {
        int4 r0 = __ldg(reinterpret_cast<const int4*>(row + e));
        int4 r1 = __ldg(reinterpret_cast<const int4*>(row + e + 4));
        int4 c0 = __ldg(reinterpret_cast<const int4*>(col + e));
        int4 c1 = __ldg(reinterpret_cast<const int4*>(col + e + 4));

        float2 s0 = __ldg(reinterpret_cast<const float2*>(g_s) + r0.x);
        float2 s1 = __ldg(reinterpret_cast<const float2*>(g_s) + r0.y);
        float2 s2 = __ldg(reinterpret_cast<const float2*>(g_s) + r0.z);
        float2 s3 = __ldg(reinterpret_cast<const float2*>(g_s) + r0.w);
        float2 s4 = __ldg(reinterpret_cast<const float2*>(g_s) + r1.x);
        float2 s5 = __ldg(reinterpret_cast<const float2*>(g_s) + r1.y);
        float2 s6 = __ldg(reinterpret_cast<const float2*>(g_s) + r1.z);
        float2 s7 = __ldg(reinterpret_cast<const float2*>(g_s) + r1.w);

        asm volatile("red.global.add.v2.f32 [%0], {%1, %2};"
                     :: "l"(out + (size_t)c0.x * 2), "f"(s0.x), "f"(s0.y) : "memory");
        asm volatile("red.global.add.v2.f32 [%0], {%1, %2};"
                     :: "l"(out + (size_t)c0.y * 2), "f"(s1.x), "f"(s1.y) : "memory");
        asm volatile("red.global.add.v2.f32 [%0], {%1, %2};"
                     :: "l"(out + (size_t)c0.z * 2), "f"(s2.x), "f"(s2.y) : "memory");
        asm volatile("red.global.add.v2.f32 [%0], {%1, %2};"
                     :: "l"(out + (size_t)c0.w * 2), "f"(s3.x), "f"(s3.y) : "memory");
        asm volatile("red.global.add.v2.f32 [%0], {%1, %2};"
                     :: "l"(out + (size_t)c1.x * 2), "f"(s4.x), "f"(s4.y) : "memory");
        asm volatile("red.global.add.v2.f32 [%0], {%1, %2};"
                     :: "l"(out + (size_t)c1.y * 2), "f"(s5.x), "f"(s5.y) : "memory");
        asm volatile("red.global.add.v2.f32 [%0], {%1, %2};"
                     :: "l"(out + (size_t)c1.z * 2), "f"(s6.x), "f"(s6.y) : "memory");
        asm volatile("red.global.add.v2.f32 [%0], {%1, %2};"
                     :: "l"(out + (size_t)c1.w * 2), "f"(s7.x), "f"(s7.y) : "memory");
    } else {
        for (; e < n_edges; e++) {
            int r1 = row[e], c1 = col[e];
            float2 sv = __ldg(reinterpret_cast<const float2*>(g_s) + r1);
            asm volatile("red.global.add.v2.f32 [%0], {%1, %2};"
                         :: "l"(out + (size_t)c1 * 2), "f"(sv.x), "f"(sv.y) : "memory");
        }
    }
}

// ---------------------------------------------------------------------------
// K4: finalize: out = out*dinv + c
__global__ void finalize_kernel(float* __restrict__ out, int n_nodes) {
    int i = (blockIdx.x * blockDim.x + threadIdx.x) * 2;
    float c0 = g_c[0], c1 = g_c[1];
    if (i + 1 < n_nodes) {
        float4 a = *reinterpret_cast<float4*>(out + i * 2);
        float2 d = *reinterpret_cast<float2*>(g_dinv + i);
        a.x = a.x * d.x + c0;  a.y = a.y * d.x + c1;
        a.z = a.z * d.y + c0;  a.w = a.w * d.y + c1;
        *reinterpret_cast<float4*>(out + i * 2) = a;
    } else if (i < n_nodes) {
        float di = g_dinv[i];
        float2 a = reinterpret_cast<float2*>(out)[i];
        a.x = a.x * di + c0;
        a.y = a.y * di + c1;
        reinterpret_cast<float2*>(out)[i] = a;
    }
}

// ---------------------------------------------------------------------------
extern "C" void kernel_launch(void* const* d_in, const int* in_sizes, int n_in,
                              void* d_out, int out_size) {
    const float* x  = (const float*)d_in[0];
    const int*   ei = (const int*)d_in[1];   // [2, E]
    const float* W1 = (const float*)d_in[2];
    const float* b1 = (const float*)d_in[3];
    const float* W2 = (const float*)d_in[4];
    const float* b2 = (const float*)d_in[5];
    float* out = (float*)d_out;

    const int n_edges = in_sizes[1] / 2;
    const int n_nodes = out_size / OUT_CH;
    const int* row = ei;             // source nodes
    const int* col = ei + n_edges;   // target nodes

    int dev = 0, sms = 148;
    cudaGetDevice(&dev);
    cudaDeviceGetAttribute(&sms, cudaDevAttrMultiProcessorCount, dev);

    const int T = 256;
    const int grid = 2 * sms;        // persistent-ish: all resident (256 thr, 2/SM)
    const int node2_blocks = ((n_nodes + 1) / 2 + T - 1) / T;
    const int edge8_threads = (n_edges + 7) / 8;

    fused_kernel<<<grid, T>>>(x, row, col, W1, W2, n_edges, n_nodes);
    nodeprep_kernel<<<node2_blocks, T>>>(b1, W2, b2, out, n_nodes);
    scatter_kernel<<<(edge8_threads + T - 1) / T, T>>>(row, col, out, n_edges);
    finalize_kernel<<<node2_blocks, T>>>(out, n_nodes);
}

// round 8
// speedup vs baseline: 1.6049x; 1.1804x over previous
#include <cuda_runtime.h>
#include <cstdint>

#define IN_CH   512
#define HID     16
#define OUT_CH  2
#define MAX_NODES 100000
#define DEG_BLOCKS 160

// Scratch (device globals; no allocation allowed)
__device__ __align__(16) float g_s[MAX_NODES * 2];   // y = x@W12, then s = y*dinv
__device__ __align__(16) int   g_deg[MAX_NODES];     // zero-init; re-zeroed in nodeprep
__device__ __align__(16) float g_dinv[MAX_NODES];    // 1/sqrt(deg+1)
__device__ __align__(16) float g_w0[IN_CH];          // col 0 of W12 = W1@W2
__device__ __align__(16) float g_w1[IN_CH];          // col 1 of W12
__device__ float g_c[2];                             // b1@W2 + b2
__device__ unsigned g_work = 0;                      // GEMM group pool (reset in nodeprep)

// ---------------------------------------------------------------------------
// K1: fold weights/bias (single block, 512 threads)
__global__ void prep_kernel(const float* __restrict__ W1,
                            const float* __restrict__ b1,
                            const float* __restrict__ W2,
                            const float* __restrict__ b2) {
    int t = threadIdx.x;                 // 512 threads == IN_CH
    float s0 = 0.0f, s1 = 0.0f;
#pragma unroll
    for (int h = 0; h < HID; h++) {
        float w = W1[t * HID + h];
        s0 += w * W2[h * OUT_CH + 0];
        s1 += w * W2[h * OUT_CH + 1];
    }
    g_w0[t] = s0;
    g_w1[t] = s1;
    if (t < OUT_CH) {
        float c = b2[t];
#pragma unroll
        for (int h = 0; h < HID; h++) c += b1[h] * W2[h * OUT_CH + t];
        g_c[t] = c;
    }
}

// ---------------------------------------------------------------------------
// K2: persistent fused kernel (grid = 2*SMs, all resident)
//   blocks [0, DEG_BLOCKS): first drain degree atomics over their partition,
//   then ALL blocks pull 4-row GEMM groups from the g_work pool (no wave
//   tail, no idle deg slots).
__global__ void __launch_bounds__(256, 2)
fused_kernel(const float* __restrict__ x,
             const int* __restrict__ col,
             int n_edges, int n_nodes) {
    const int tid  = threadIdx.x;
    const int lane = tid & 31;

    if ((int)blockIdx.x < DEG_BLOCKS) {
        // ---- degree atomics over edges (grid-stride within partition) ----
        int n4 = n_edges >> 2;
        int stride = DEG_BLOCKS * blockDim.x;
        for (int t = blockIdx.x * blockDim.x + tid; t < n4; t += stride) {
            int4 c = __ldg(reinterpret_cast<const int4*>(col) + t);
            atomicAdd(&g_deg[c.x], 1);
            atomicAdd(&g_deg[c.y], 1);
            atomicAdd(&g_deg[c.z], 1);
            atomicAdd(&g_deg[c.w], 1);
        }
        if (blockIdx.x == 0 && tid < (n_edges & 3))
            atomicAdd(&g_deg[col[(n4 << 2) + tid]], 1);
        // fall through to GEMM pool
    }

    // ---- GEMM: warp pulls 4-row groups from the global pool ----
    float4 wa[4], wb[4];
#pragma unroll
    for (int j = 0; j < 4; j++) {
        int idx = lane + 32 * j;
        wa[j] = reinterpret_cast<const float4*>(g_w0)[idx];
        wb[j] = reinterpret_cast<const float4*>(g_w1)[idx];
    }

    const float4* x4 = reinterpret_cast<const float4*>(x);
    const int n_groups = (n_nodes + 3) >> 2;

    for (;;) {
        unsigned g;
        if (lane == 0) g = atomicAdd(&g_work, 1u);
        g = __shfl_sync(0xFFFFFFFFu, g, 0);
        if (g >= (unsigned)n_groups) break;

        const int rbase = (int)g * 4;
        if (rbase + 4 <= n_nodes) {
            float4 v[4][4];
#pragma unroll
            for (int r = 0; r < 4; r++) {
                const float4* xr = x4 + (size_t)(rbase + r) * (IN_CH / 4);
#pragma unroll
                for (int j = 0; j < 4; j++) v[r][j] = __ldg(xr + lane + 32 * j);
            }
            float s00 = 0.f, s01 = 0.f, s10 = 0.f, s11 = 0.f;
            float s20 = 0.f, s21 = 0.f, s30 = 0.f, s31 = 0.f;
#pragma unroll
            for (int j = 0; j < 4; j++) {
                s00 += v[0][j].x * wa[j].x + v[0][j].y * wa[j].y + v[0][j].z * wa[j].z + v[0][j].w * wa[j].w;
                s01 += v[0][j].x * wb[j].x + v[0][j].y * wb[j].y + v[0][j].z * wb[j].z + v[0][j].w * wb[j].w;
                s10 += v[1][j].x * wa[j].x + v[1][j].y * wa[j].y + v[1][j].z * wa[j].z + v[1][j].w * wa[j].w;
                s11 += v[1][j].x * wb[j].x + v[1][j].y * wb[j].y + v[1][j].z * wb[j].z + v[1][j].w * wb[j].w;
                s20 += v[2][j].x * wa[j].x + v[2][j].y * wa[j].y + v[2][j].z * wa[j].z + v[2][j].w * wa[j].w;
                s21 += v[2][j].x * wb[j].x + v[2][j].y * wb[j].y + v[2][j].z * wb[j].z + v[2][j].w * wb[j].w;
                s30 += v[3][j].x * wa[j].x + v[3][j].y * wa[j].y + v[3][j].z * wa[j].z + v[3][j].w * wa[j].w;
                s31 += v[3][j].x * wb[j].x + v[3][j].y * wb[j].y + v[3][j].z * wb[j].z + v[3][j].w * wb[j].w;
            }
#pragma unroll
            for (int off = 16; off > 0; off >>= 1) {
                s00 += __shfl_xor_sync(0xFFFFFFFFu, s00, off);
                s01 += __shfl_xor_sync(0xFFFFFFFFu, s01, off);
                s10 += __shfl_xor_sync(0xFFFFFFFFu, s10, off);
                s11 += __shfl_xor_sync(0xFFFFFFFFu, s11, off);
                s20 += __shfl_xor_sync(0xFFFFFFFFu, s20, off);
                s21 += __shfl_xor_sync(0xFFFFFFFFu, s21, off);
                s30 += __shfl_xor_sync(0xFFFFFFFFu, s30, off);
                s31 += __shfl_xor_sync(0xFFFFFFFFu, s31, off);
            }
            if (lane < 4) {
                float o0, o1;
                if      (lane == 0) { o0 = s00; o1 = s01; }
                else if (lane == 1) { o0 = s10; o1 = s11; }
                else if (lane == 2) { o0 = s20; o1 = s21; }
                else                { o0 = s30; o1 = s31; }
                reinterpret_cast<float2*>(g_s)[rbase + lane] = make_float2(o0, o1);
            }
        } else {
            // guarded last group (rows beyond n_nodes skipped)
            for (int r = rbase; r < n_nodes; r++) {
                const float4* xr = x4 + (size_t)r * (IN_CH / 4);
                float s0 = 0.f, s1 = 0.f;
#pragma unroll
                for (int j = 0; j < 4; j++) {
                    float4 v0 = __ldg(xr + lane + 32 * j);
                    s0 += v0.x * wa[j].x + v0.y * wa[j].y + v0.z * wa[j].z + v0.w * wa[j].w;
                    s1 += v0.x * wb[j].x + v0.y * wb[j].y + v0.z * wb[j].z + v0.w * wb[j].w;
                }
#pragma unroll
                for (int off = 16; off > 0; off >>= 1) {
                    s0 += __shfl_xor_sync(0xFFFFFFFFu, s0, off);
                    s1 += __shfl_xor_sync(0xFFFFFFFFu, s1, off);
                }
                if (lane == 0)
                    reinterpret_cast<float2*>(g_s)[r] = make_float2(s0, s1);
            }
        }
    }
}

// ---------------------------------------------------------------------------
// K3: node prep: dinv = rsqrt(deg+1); s = y*dinv; out = s; re-zero deg/pool
__global__ void nodeprep_kernel(float* __restrict__ out, int n_nodes) {
    if (blockIdx.x == 0 && threadIdx.x == 0) g_work = 0;   // pool ready for replay
    int i = (blockIdx.x * blockDim.x + threadIdx.x) * 2;
    if (i + 1 < n_nodes) {
        float4 y = *reinterpret_cast<float4*>(g_s + i * 2);
        float d0 = rsqrtf((float)(g_deg[i] + 1));
        float d1 = rsqrtf((float)(g_deg[i + 1] + 1));
        *reinterpret_cast<int2*>(g_deg + i) = make_int2(0, 0);  // ready for replay
        y.x *= d0; y.y *= d0; y.z *= d1; y.w *= d1;
        *reinterpret_cast<float4*>(g_s + i * 2) = y;
        *reinterpret_cast<float4*>(out + i * 2) = y;   // accumulator seeded with s[c]
        *reinterpret_cast<float2*>(g_dinv + i) = make_float2(d0, d1);
    } else if (i < n_nodes) {
        float di = rsqrtf((float)(g_deg[i] + 1));
        g_deg[i] = 0;
        g_dinv[i] = di;
        float2 y = reinterpret_cast<const float2*>(g_s)[i];
        float2 s = make_float2(y.x * di, y.y * di);
        reinterpret_cast<float2*>(g_s)[i] = s;
        reinterpret_cast<float2*>(out)[i] = s;
    }
}

// ---------------------------------------------------------------------------
// K4: edge scatter  out[c] += s[r]   (4 edges/thread — measured-good config)
__global__ void scatter_kernel(const int* __restrict__ row,
                               const int* __restrict__ col,
                               float* __restrict__ out, int n_edges) {
    int t = blockIdx.x * blockDim.x + threadIdx.x;
    int e = t * 4;
    if (e + 3 < n_edges) {
        int4 r = *reinterpret_cast<const int4*>(row + e);
        int4 c = *reinterpret_cast<const int4*>(col + e);

        float2 sx = __ldg(reinterpret_cast<const float2*>(g_s) + r.x);
        float2 sy = __ldg(reinterpret_cast<const float2*>(g_s) + r.y);
        float2 sz = __ldg(reinterpret_cast<const float2*>(g_s) + r.z);
        float2 sw = __ldg(reinterpret_cast<const float2*>(g_s) + r.w);

        asm volatile("red.global.add.v2.f32 [%0], {%1, %2};"
                     :: "l"(out + (size_t)c.x * 2), "f"(sx.x), "f"(sx.y) : "memory");
        asm volatile("red.global.add.v2.f32 [%0], {%1, %2};"
                     :: "l"(out + (size_t)c.y * 2), "f"(sy.x), "f"(sy.y) : "memory");
        asm volatile("red.global.add.v2.f32 [%0], {%1, %2};"
                     :: "l"(out + (size_t)c.z * 2), "f"(sz.x), "f"(sz.y) : "memory");
        asm volatile("red.global.add.v2.f32 [%0], {%1, %2};"
                     :: "l"(out + (size_t)c.w * 2), "f"(sw.x), "f"(sw.y) : "memory");
    } else {
        for (; e < n_edges; e++) {
            int r1 = row[e], c1 = col[e];
            float2 sv = __ldg(reinterpret_cast<const float2*>(g_s) + r1);
            asm volatile("red.global.add.v2.f32 [%0], {%1, %2};"
                         :: "l"(out + (size_t)c1 * 2), "f"(sv.x), "f"(sv.y) : "memory");
        }
    }
}

// ---------------------------------------------------------------------------
// K5: finalize: out = out*dinv + c
__global__ void finalize_kernel(float* __restrict__ out, int n_nodes) {
    int i = (blockIdx.x * blockDim.x + threadIdx.x) * 2;
    float c0 = g_c[0], c1 = g_c[1];
    if (i + 1 < n_nodes) {
        float4 a = *reinterpret_cast<float4*>(out + i * 2);
        float2 d = *reinterpret_cast<float2*>(g_dinv + i);
        a.x = a.x * d.x + c0;  a.y = a.y * d.x + c1;
        a.z = a.z * d.y + c0;  a.w = a.w * d.y + c1;
        *reinterpret_cast<float4*>(out + i * 2) = a;
    } else if (i < n_nodes) {
        float di = g_dinv[i];
        float2 a = reinterpret_cast<float2*>(out)[i];
        a.x = a.x * di + c0;
        a.y = a.y * di + c1;
        reinterpret_cast<float2*>(out)[i] = a;
    }
}

// ---------------------------------------------------------------------------
extern "C" void kernel_launch(void* const* d_in, const int* in_sizes, int n_in,
                              void* d_out, int out_size) {
    const float* x  = (const float*)d_in[0];
    const int*   ei = (const int*)d_in[1];   // [2, E]
    const float* W1 = (const float*)d_in[2];
    const float* b1 = (const float*)d_in[3];
    const float* W2 = (const float*)d_in[4];
    const float* b2 = (const float*)d_in[5];
    float* out = (float*)d_out;

    const int n_edges = in_sizes[1] / 2;
    const int n_nodes = out_size / OUT_CH;
    const int* row = ei;             // source nodes
    const int* col = ei + n_edges;   // target nodes

    int dev = 0, sms = 148;
    cudaGetDevice(&dev);
    cudaDeviceGetAttribute(&sms, cudaDevAttrMultiProcessorCount, dev);

    const int T = 256;
    const int grid = 2 * sms;                      // all resident (256 thr, 2/SM)
    const int node2_blocks = ((n_nodes + 1) / 2 + T - 1) / T;
    const int edge_threads = (n_edges + 3) / 4;

    prep_kernel<<<1, 512>>>(W1, b1, W2, b2);
    fused_kernel<<<grid, T>>>(x, col, n_edges, n_nodes);
    nodeprep_kernel<<<node2_blocks, T>>>(out, n_nodes);
    scatter_kernel<<<(edge_threads + T - 1) / T, T>>>(row, col, out, n_edges);
    finalize_kernel<<<node2_blocks, T>>>(out, n_nodes);
}

// round 9
// speedup vs baseline: 1.7216x; 1.0727x over previous
#include <cuda_runtime.h>
#include <cstdint>

#define IN_CH   512
#define HID     16
#define OUT_CH  2
#define MAX_NODES 100000
#define DEG_BLOCKS 512

// Scratch (device globals; no allocation allowed)
__device__ __align__(16) float g_s[MAX_NODES * 2];   // y = x@W12, then s = y*dinv
__device__ __align__(16) int   g_deg[MAX_NODES];     // zero-init; re-zeroed in finalize
__device__ __align__(16) float g_dinv[MAX_NODES];    // 1/sqrt(deg+1)
__device__ __align__(16) float g_w0[IN_CH];          // col 0 of W12 = W1@W2
__device__ __align__(16) float g_w1[IN_CH];          // col 1 of W12
__device__ float g_c[2];                             // b1@W2 + b2

// ---------------------------------------------------------------------------
// K1: fold weights/bias (single block, 512 threads)
__global__ void prep_kernel(const float* __restrict__ W1,
                            const float* __restrict__ b1,
                            const float* __restrict__ W2,
                            const float* __restrict__ b2) {
    int t = threadIdx.x;                 // 512 threads == IN_CH
    float s0 = 0.0f, s1 = 0.0f;
#pragma unroll
    for (int h = 0; h < HID; h++) {
        float w = W1[t * HID + h];
        s0 += w * W2[h * OUT_CH + 0];
        s1 += w * W2[h * OUT_CH + 1];
    }
    g_w0[t] = s0;
    g_w1[t] = s1;
    if (t < OUT_CH) {
        float c = b2[t];
#pragma unroll
        for (int h = 0; h < HID; h++) c += b1[h] * W2[h * OUT_CH + t];
        g_c[t] = c;
    }
}

// ---------------------------------------------------------------------------
// K2: fused  deg (L2-atomic bound, 512 blocks)  ||  GEMM (DRAM bound, rest)
__global__ void __launch_bounds__(256, 2)
fused_kernel(const float* __restrict__ x,
             const int* __restrict__ col,
             int n_edges, int n_nodes) {
    if ((int)blockIdx.x < DEG_BLOCKS) {
        // ---- degree atomics over edges; indices read evict-first ----
        int n4 = n_edges >> 2;
        int stride = DEG_BLOCKS * blockDim.x;
        for (int t = blockIdx.x * blockDim.x + threadIdx.x; t < n4; t += stride) {
            int4 c = __ldcs(reinterpret_cast<const int4*>(col) + t);
            atomicAdd(&g_deg[c.x], 1);
            atomicAdd(&g_deg[c.y], 1);
            atomicAdd(&g_deg[c.z], 1);
            atomicAdd(&g_deg[c.w], 1);
        }
        if (blockIdx.x == 0 && threadIdx.x < (n_edges & 3)) {
            atomicAdd(&g_deg[col[(n4 << 2) + threadIdx.x]], 1);
        }
        return;
    }

    // ---- GEMM part: warp computes 4 consecutive rows, x evict-first ----
    const int lane  = threadIdx.x & 31;
    const int gwarp = (((blockIdx.x - DEG_BLOCKS) * blockDim.x) + threadIdx.x) >> 5;
    const int rbase = gwarp * 4;
    if (rbase >= n_nodes) return;

    float4 wa[4], wb[4];
#pragma unroll
    for (int j = 0; j < 4; j++) {
        int idx = lane + 32 * j;
        wa[j] = reinterpret_cast<const float4*>(g_w0)[idx];
        wb[j] = reinterpret_cast<const float4*>(g_w1)[idx];
    }

    const float4* x4 = reinterpret_cast<const float4*>(x);

    if (rbase + 4 <= n_nodes) {
        float4 v[4][4];
#pragma unroll
        for (int r = 0; r < 4; r++) {
            const float4* xr = x4 + (size_t)(rbase + r) * (IN_CH / 4);
#pragma unroll
            for (int j = 0; j < 4; j++) v[r][j] = __ldcs(xr + lane + 32 * j);
        }
        float s00 = 0.f, s01 = 0.f, s10 = 0.f, s11 = 0.f;
        float s20 = 0.f, s21 = 0.f, s30 = 0.f, s31 = 0.f;
#pragma unroll
        for (int j = 0; j < 4; j++) {
            s00 += v[0][j].x * wa[j].x + v[0][j].y * wa[j].y + v[0][j].z * wa[j].z + v[0][j].w * wa[j].w;
            s01 += v[0][j].x * wb[j].x + v[0][j].y * wb[j].y + v[0][j].z * wb[j].z + v[0][j].w * wb[j].w;
            s10 += v[1][j].x * wa[j].x + v[1][j].y * wa[j].y + v[1][j].z * wa[j].z + v[1][j].w * wa[j].w;
            s11 += v[1][j].x * wb[j].x + v[1][j].y * wb[j].y + v[1][j].z * wb[j].z + v[1][j].w * wb[j].w;
            s20 += v[2][j].x * wa[j].x + v[2][j].y * wa[j].y + v[2][j].z * wa[j].z + v[2][j].w * wa[j].w;
            s21 += v[2][j].x * wb[j].x + v[2][j].y * wb[j].y + v[2][j].z * wb[j].z + v[2][j].w * wb[j].w;
            s30 += v[3][j].x * wa[j].x + v[3][j].y * wa[j].y + v[3][j].z * wa[j].z + v[3][j].w * wa[j].w;
            s31 += v[3][j].x * wb[j].x + v[3][j].y * wb[j].y + v[3][j].z * wb[j].z + v[3][j].w * wb[j].w;
        }
#pragma unroll
        for (int off = 16; off > 0; off >>= 1) {
            s00 += __shfl_xor_sync(0xFFFFFFFFu, s00, off);
            s01 += __shfl_xor_sync(0xFFFFFFFFu, s01, off);
            s10 += __shfl_xor_sync(0xFFFFFFFFu, s10, off);
            s11 += __shfl_xor_sync(0xFFFFFFFFu, s11, off);
            s20 += __shfl_xor_sync(0xFFFFFFFFu, s20, off);
            s21 += __shfl_xor_sync(0xFFFFFFFFu, s21, off);
            s30 += __shfl_xor_sync(0xFFFFFFFFu, s30, off);
            s31 += __shfl_xor_sync(0xFFFFFFFFu, s31, off);
        }
        if (lane < 4) {
            float o0, o1;
            if      (lane == 0) { o0 = s00; o1 = s01; }
            else if (lane == 1) { o0 = s10; o1 = s11; }
            else if (lane == 2) { o0 = s20; o1 = s21; }
            else                { o0 = s30; o1 = s31; }
            reinterpret_cast<float2*>(g_s)[rbase + lane] = make_float2(o0, o1);
        }
    } else {
        for (int row = rbase; row < n_nodes; row++) {
            const float4* xr = x4 + (size_t)row * (IN_CH / 4);
            float s0 = 0.f, s1 = 0.f;
#pragma unroll
            for (int j = 0; j < 4; j++) {
                float4 v0 = __ldcs(xr + lane + 32 * j);
                s0 += v0.x * wa[j].x + v0.y * wa[j].y + v0.z * wa[j].z + v0.w * wa[j].w;
                s1 += v0.x * wb[j].x + v0.y * wb[j].y + v0.z * wb[j].z + v0.w * wb[j].w;
            }
#pragma unroll
            for (int off = 16; off > 0; off >>= 1) {
                s0 += __shfl_xor_sync(0xFFFFFFFFu, s0, off);
                s1 += __shfl_xor_sync(0xFFFFFFFFu, s1, off);
            }
            if (lane == 0)
                reinterpret_cast<float2*>(g_s)[row] = make_float2(s0, s1);
        }
    }
}

// ---------------------------------------------------------------------------
// K3: node prep (2 nodes/thread): dinv = rsqrt(deg+1); s = y*dinv; out = s
__global__ void nodeprep_kernel(float* __restrict__ out, int n_nodes) {
    int i = (blockIdx.x * blockDim.x + threadIdx.x) * 2;
    if (i + 1 < n_nodes) {
        float4 y = *reinterpret_cast<float4*>(g_s + i * 2);
        float d0 = rsqrtf((float)(g_deg[i] + 1));
        float d1 = rsqrtf((float)(g_deg[i + 1] + 1));
        y.x *= d0; y.y *= d0; y.z *= d1; y.w *= d1;
        *reinterpret_cast<float4*>(g_s + i * 2) = y;
        *reinterpret_cast<float4*>(out + i * 2) = y;   // accumulator seeded with s[c]
        *reinterpret_cast<float2*>(g_dinv + i) = make_float2(d0, d1);
    } else if (i < n_nodes) {
        float di = rsqrtf((float)(g_deg[i] + 1));
        g_dinv[i] = di;
        float2 y = reinterpret_cast<const float2*>(g_s)[i];
        float2 s = make_float2(y.x * di, y.y * di);
        reinterpret_cast<float2*>(g_s)[i] = s;
        reinterpret_cast<float2*>(out)[i] = s;
    }
}

// ---------------------------------------------------------------------------
// K4: edge scatter  out[c] += s[r]   (4 edges/thread; indices evict-first,
//     gathers cached — keep L2 for g_s/out)
__global__ void scatter_kernel(const int* __restrict__ row,
                               const int* __restrict__ col,
                               float* __restrict__ out, int n_edges) {
    int t = blockIdx.x * blockDim.x + threadIdx.x;
    int e = t * 4;
    if (e + 3 < n_edges) {
        int4 r = __ldcs(reinterpret_cast<const int4*>(row + e));
        int4 c = __ldcs(reinterpret_cast<const int4*>(col + e));

        float2 sx = __ldg(reinterpret_cast<const float2*>(g_s) + r.x);
        float2 sy = __ldg(reinterpret_cast<const float2*>(g_s) + r.y);
        float2 sz = __ldg(reinterpret_cast<const float2*>(g_s) + r.z);
        float2 sw = __ldg(reinterpret_cast<const float2*>(g_s) + r.w);

        asm volatile("red.global.add.v2.f32 [%0], {%1, %2};"
                     :: "l"(out + (size_t)c.x * 2), "f"(sx.x), "f"(sx.y) : "memory");
        asm volatile("red.global.add.v2.f32 [%0], {%1, %2};"
                     :: "l"(out + (size_t)c.y * 2), "f"(sy.x), "f"(sy.y) : "memory");
        asm volatile("red.global.add.v2.f32 [%0], {%1, %2};"
                     :: "l"(out + (size_t)c.z * 2), "f"(sz.x), "f"(sz.y) : "memory");
        asm volatile("red.global.add.v2.f32 [%0], {%1, %2};"
                     :: "l"(out + (size_t)c.w * 2), "f"(sw.x), "f"(sw.y) : "memory");
    } else {
        for (; e < n_edges; e++) {
            int r1 = row[e], c1 = col[e];
            float2 sv = __ldg(reinterpret_cast<const float2*>(g_s) + r1);
            asm volatile("red.global.add.v2.f32 [%0], {%1, %2};"
                         :: "l"(out + (size_t)c1 * 2), "f"(sv.x), "f"(sv.y) : "memory");
        }
    }
}

// ---------------------------------------------------------------------------
// K5: finalize (2 nodes/thread): out = out*dinv + c; re-zero g_deg
__global__ void finalize_kernel(float* __restrict__ out, int n_nodes) {
    int i = (blockIdx.x * blockDim.x + threadIdx.x) * 2;
    float c0 = g_c[0], c1 = g_c[1];
    if (i + 1 < n_nodes) {
        float4 a = *reinterpret_cast<float4*>(out + i * 2);
        float2 d = *reinterpret_cast<float2*>(g_dinv + i);
        a.x = a.x * d.x + c0;  a.y = a.y * d.x + c1;
        a.z = a.z * d.y + c0;  a.w = a.w * d.y + c1;
        *reinterpret_cast<float4*>(out + i * 2) = a;
        *reinterpret_cast<int2*>(g_deg + i) = make_int2(0, 0);  // ready for next run
    } else if (i < n_nodes) {
        float di = g_dinv[i];
        float2 a = reinterpret_cast<float2*>(out)[i];
        a.x = a.x * di + c0;
        a.y = a.y * di + c1;
        reinterpret_cast<float2*>(out)[i] = a;
        g_deg[i] = 0;
    }
}

// ---------------------------------------------------------------------------
extern "C" void kernel_launch(void* const* d_in, const int* in_sizes, int n_in,
                              void* d_out, int out_size) {
    const float* x  = (const float*)d_in[0];
    const int*   ei = (const int*)d_in[1];   // [2, E]
    const float* W1 = (const float*)d_in[2];
    const float* b1 = (const float*)d_in[3];
    const float* W2 = (const float*)d_in[4];
    const float* b2 = (const float*)d_in[5];
    float* out = (float*)d_out;

    const int n_edges = in_sizes[1] / 2;
    const int n_nodes = out_size / OUT_CH;
    const int* row = ei;             // source nodes
    const int* col = ei + n_edges;   // target nodes

    const int T = 256;
    const int edge_threads = (n_edges + 3) / 4;
    const int gemm_blocks = (n_nodes + 4 * (T / 32) - 1) / (4 * (T / 32));  // 4 rows/warp
    const int node2_blocks = ((n_nodes + 1) / 2 + T - 1) / T;

    prep_kernel<<<1, 512>>>(W1, b1, W2, b2);
    fused_kernel<<<DEG_BLOCKS + gemm_blocks, T>>>(x, col, n_edges, n_nodes);
    nodeprep_kernel<<<node2_blocks, T>>>(out, n_nodes);
    scatter_kernel<<<(edge_threads + T - 1) / T, T>>>(row, col, out, n_edges);
    finalize_kernel<<<node2_blocks, T>>>(out, n_nodes);
}